// round 8
// baseline (speedup 1.0000x reference)
#include <cuda_runtime.h>
#include <float.h>

// Fused: out[b,c,y,x] = relu( p1[b,c%128,y,x] + p2[b,c%64,y,x]
//                           + p3[b,c%32,y,x] + p4[b,c%16,y,x] + ff[b,c,y,x] )
// pk = non-overlapping max-pool of input_tensor_k.
//
// HX=4: one CTA per (b, y, x-sixth). 2304 CTAs x 256 thr at occ 4 -> ~3.9
// waves of work-stealing to amortize between-SM completion spread. Warp-
// coalesced LDG.128s (t4: 512B, t3: 512B, t2: 8x64B, t1: 16x32B chunks) with
// shfl_xor window reductions; __ldcs/__stcs streaming hints throughout.

#define HW 24
#define HX 4
#define THREADS 256
#define FULL 0xFFFFFFFFu

__device__ __forceinline__ float hmax4(float4 v) {
    return fmaxf(fmaxf(v.x, v.y), fmaxf(v.z, v.w));
}

__device__ __forceinline__ float4 ldcs4(const float* p) {
    return __ldcs(reinterpret_cast<const float4*>(p));
}

__global__ __launch_bounds__(THREADS, 4)
void fused_ffblock_kernel(const float* __restrict__ t1,   // [16,128,48,48]
                          const float* __restrict__ t2,   // [16, 64,96,96]
                          const float* __restrict__ t3,   // [16, 32,192,192]
                          const float* __restrict__ t4,   // [16, 16,384,384]
                          const float* __restrict__ ff,   // [16,256,24,24]
                          float* __restrict__ out)        // [16,256,24,24]
{
    const int bx   = blockIdx.x;
    const int xh   = bx % 6;
    const int y    = (bx / 6) % HW;
    const int b    = bx / (6 * HW);
    const int tid  = threadIdx.x;
    const int w    = tid >> 5;
    const int lane = tid & 31;
    const int xbase = xh * HX;

    __shared__ __align__(16) float p4s[16 * HX];
    __shared__ __align__(16) float p3s[32 * HX];
    __shared__ __align__(16) float p2s[64 * HX];
    __shared__ __align__(16) float p1s[128 * HX];

    // ---- t4: k=16, 16 ch x 4 windows. Warp handles c = w, w+8.
    // Each LDG: 2 rows x 256B (rp = row parity, sl = 16B slot in row).
    #pragma unroll
    for (int ci = 0; ci < 2; ++ci) {
        const int c  = w + ci * 8;
        const int rp = lane >> 4;
        const int sl = lane & 15;
        const float* base = t4 + (((b * 16 + c) * 384 + y * 16 + rp) * 384)
                               + xbase * 16 + sl * 4;
        float4 m = make_float4(-FLT_MAX, -FLT_MAX, -FLT_MAX, -FLT_MAX);
        #pragma unroll 4
        for (int i = 0; i < 8; ++i) {            // rows 2i+rp
            float4 v = ldcs4(base + i * 768);
            m.x = fmaxf(m.x, v.x); m.y = fmaxf(m.y, v.y);
            m.z = fmaxf(m.z, v.z); m.w = fmaxf(m.w, v.w);
        }
        float s = hmax4(m);                        // 16B slot max
        s = fmaxf(s, __shfl_xor_sync(FULL, s, 1)); // window = 4 slots (64B)
        s = fmaxf(s, __shfl_xor_sync(FULL, s, 2));
        s = fmaxf(s, __shfl_xor_sync(FULL, s, 16)); // combine row parities
        if (rp == 0 && (sl & 3) == 0) p4s[c * HX + (sl >> 2)] = s;
    }

    // ---- t3: k=8, 32 ch x 4 windows. Warp handles c = w + 8*ci.
    // Each LDG: 4 rows x 128B (row = lane>>3, sl = 16B slot).
    #pragma unroll
    for (int ci = 0; ci < 4; ++ci) {
        const int c   = w + ci * 8;
        const int row = lane >> 3;
        const int sl  = lane & 7;
        const float* base = t3 + (((b * 32 + c) * 192 + y * 8 + row) * 192)
                               + xbase * 8 + sl * 4;
        float4 m = make_float4(-FLT_MAX, -FLT_MAX, -FLT_MAX, -FLT_MAX);
        #pragma unroll
        for (int i = 0; i < 2; ++i) {            // rows 4i+row
            float4 v = ldcs4(base + i * 768);
            m.x = fmaxf(m.x, v.x); m.y = fmaxf(m.y, v.y);
            m.z = fmaxf(m.z, v.z); m.w = fmaxf(m.w, v.w);
        }
        float s = hmax4(m);
        s = fmaxf(s, __shfl_xor_sync(FULL, s, 1));  // window = 2 slots (32B)
        s = fmaxf(s, __shfl_xor_sync(FULL, s, 8));  // combine 4 rows
        s = fmaxf(s, __shfl_xor_sync(FULL, s, 16));
        if (row == 0 && (sl & 1) == 0) p3s[c * HX + (sl >> 1)] = s;
    }

    // ---- t2: k=4, 64 ch x 4 windows. Warp handles 2 ch per LDG, 8 ch total.
    // co = lane>>4 (channel), row = (lane>>2)&3, sl = lane&3 (= window).
    #pragma unroll
    for (int ci = 0; ci < 4; ++ci) {
        const int co  = lane >> 4;
        const int c   = w * 8 + ci * 2 + co;
        const int row = (lane >> 2) & 3;
        const int sl  = lane & 3;
        const float* p = t2 + (((b * 64 + c) * 96 + y * 4 + row) * 96)
                            + xbase * 4 + sl * 4;
        float4 v = ldcs4(p);
        float s = hmax4(v);                        // window-row max (4 wide)
        s = fmaxf(s, __shfl_xor_sync(FULL, s, 4)); // combine 4 rows
        s = fmaxf(s, __shfl_xor_sync(FULL, s, 8));
        if (row == 0) p2s[c * HX + sl] = s;
    }

    // ---- t1: k=2, 128 ch x 4 windows. Warp handles 8 ch per LDG, 16 ch total.
    // c_off = lane>>2, row = (lane>>1)&1, sl = lane&1 (16B = 2 windows).
    #pragma unroll
    for (int ci = 0; ci < 2; ++ci) {
        const int c   = w * 16 + ci * 8 + (lane >> 2);
        const int row = (lane >> 1) & 1;
        const int sl  = lane & 1;
        const float* p = t1 + (((b * 128 + c) * 48 + y * 2 + row) * 48)
                            + xbase * 2 + sl * 4;
        float4 v = ldcs4(p);
        float o0 = fmaxf(v.x, v.y);
        float o1 = fmaxf(v.z, v.w);
        o0 = fmaxf(o0, __shfl_xor_sync(FULL, o0, 2));  // combine 2 rows
        o1 = fmaxf(o1, __shfl_xor_sync(FULL, o1, 2));
        if (row == 0) {
            p1s[c * HX + sl * 2 + 0] = o0;
            p1s[c * HX + sl * 2 + 1] = o1;
        }
    }

    __syncthreads();

    // ---- assemble: one float4 per thread (c = tid, x = xbase..xbase+3).
    {
        const int c  = tid;
        const int c1 = c & 127, c2 = c & 63, c3 = c & 31, c4 = c & 15;
        const int g  = ((b * 256 + c) * HW + y) * HW + xbase;

        float4 f  = __ldcs(reinterpret_cast<const float4*>(ff + g));
        float4 a1 = *reinterpret_cast<const float4*>(&p1s[c1 * HX]);
        float4 a2 = *reinterpret_cast<const float4*>(&p2s[c2 * HX]);
        float4 a3 = *reinterpret_cast<const float4*>(&p3s[c3 * HX]);
        float4 a4 = *reinterpret_cast<const float4*>(&p4s[c4 * HX]);

        float4 r;
        r.x = fmaxf(f.x + a1.x + a2.x + a3.x + a4.x, 0.f);
        r.y = fmaxf(f.y + a1.y + a2.y + a3.y + a4.y, 0.f);
        r.z = fmaxf(f.z + a1.z + a2.z + a3.z + a4.z, 0.f);
        r.w = fmaxf(f.w + a1.w + a2.w + a3.w + a4.w, 0.f);

        __stcs(reinterpret_cast<float4*>(out + g), r);
    }
}

extern "C" void kernel_launch(void* const* d_in, const int* in_sizes, int n_in,
                              void* d_out, int out_size) {
    const float* t1 = (const float*)d_in[0];
    const float* t2 = (const float*)d_in[1];
    const float* t3 = (const float*)d_in[2];
    const float* t4 = (const float*)d_in[3];
    const float* ff = (const float*)d_in[4];
    float* out = (float*)d_out;

    dim3 grid(16 * HW * 6);   // 2304 CTAs; occ 4 -> ~3.9 waves (work-stealing)
    dim3 block(THREADS);
    fused_ffblock_kernel<<<grid, block>>>(t1, t2, t3, t4, ff, out);
}

// round 9
// speedup vs baseline: 1.0618x; 1.0618x over previous
#include <cuda_runtime.h>
#include <float.h>

// Fused: out[b,c,y,x] = relu( p1[b,c%128,y,x] + p2[b,c%64,y,x]
//                           + p3[b,c%32,y,x] + p4[b,c%16,y,x] + ff[b,c,y,x] )
// pk = non-overlapping max-pool of input_tensor_k.
//
// R7 geometry (HX=8, one CTA per (b,y,x-third), 1152 CTAs, occ 4, warp-
// coalesced nL=4 LDG.128 + shfl_xor reductions, __ldcs/__stcs) plus:
//  - ff prefetched into registers BEFORE __syncthreads so its DRAM reads
//    overlap the pooling phase instead of serializing after the barrier.
//  - t4 inner unroll raised to 8 (t4 = 50% of traffic).

#define HW 24
#define HX 8
#define THREADS 256
#define FULL 0xFFFFFFFFu

__device__ __forceinline__ float hmax4(float4 v) {
    return fmaxf(fmaxf(v.x, v.y), fmaxf(v.z, v.w));
}

__device__ __forceinline__ float4 ldcs4(const float* p) {
    return __ldcs(reinterpret_cast<const float4*>(p));
}

__global__ __launch_bounds__(THREADS, 4)
void fused_ffblock_kernel(const float* __restrict__ t1,   // [16,128,48,48]
                          const float* __restrict__ t2,   // [16, 64,96,96]
                          const float* __restrict__ t3,   // [16, 32,192,192]
                          const float* __restrict__ t4,   // [16, 16,384,384]
                          const float* __restrict__ ff,   // [16,256,24,24]
                          float* __restrict__ out)        // [16,256,24,24]
{
    const int bx   = blockIdx.x;
    const int xh   = bx % 3;
    const int y    = (bx / 3) % HW;
    const int b    = bx / (3 * HW);
    const int tid  = threadIdx.x;
    const int w    = tid >> 5;
    const int lane = tid & 31;
    const int xbase = xh * HX;

    __shared__ __align__(16) float p4s[16 * HX];
    __shared__ __align__(16) float p3s[32 * HX];
    __shared__ __align__(16) float p2s[64 * HX];
    __shared__ __align__(16) float p1s[128 * HX];

    // ---- prefetch ff for the two assemble items of this thread (overlaps
    // pooling-phase DRAM latency; addresses independent of pooling).
    const int row_base = ((b * 256) * HW + y) * HW + xbase;
    const int jA = tid, jB = tid + THREADS;
    const int cA = jA >> 1, xA = (jA & 1) * 4;
    const int cB = jB >> 1, xB = (jB & 1) * 4;
    const int gA = row_base + cA * (HW * HW) + xA;
    const int gB = row_base + cB * (HW * HW) + xB;
    float4 fA = __ldcs(reinterpret_cast<const float4*>(ff + gA));
    float4 fB = __ldcs(reinterpret_cast<const float4*>(ff + gB));

    // ---- t4: k=16, 16 ch. Warp handles c = w, w+8. Each LDG: 512B contiguous
    // (one window-row: 8 windows x 16 floats), 16 rows accumulated.
    #pragma unroll
    for (int ci = 0; ci < 2; ++ci) {
        const int c = w + ci * 8;
        const float* base = t4 + (((b * 16 + c) * 384 + y * 16) * 384)
                               + xbase * 16 + lane * 4;
        float4 m = make_float4(-FLT_MAX, -FLT_MAX, -FLT_MAX, -FLT_MAX);
        #pragma unroll 8
        for (int r = 0; r < 16; ++r) {
            float4 v = ldcs4(base + r * 384);
            m.x = fmaxf(m.x, v.x); m.y = fmaxf(m.y, v.y);
            m.z = fmaxf(m.z, v.z); m.w = fmaxf(m.w, v.w);
        }
        float s = hmax4(m);                        // this lane's 16B slot
        s = fmaxf(s, __shfl_xor_sync(FULL, s, 1)); // window = 4 lanes (64B)
        s = fmaxf(s, __shfl_xor_sync(FULL, s, 2));
        if ((lane & 3) == 0) p4s[c * HX + (lane >> 2)] = s;
    }

    // ---- t3: k=8, 32 ch. Warp handles c = w, w+8, w+16, w+24. Each LDG:
    // lanes 0-15 = row 2i (256B), lanes 16-31 = row 2i+1.
    #pragma unroll
    for (int ci = 0; ci < 4; ++ci) {
        const int c  = w + ci * 8;
        const int rp = lane >> 4;                 // row parity
        const int sl = lane & 15;                 // 16B slot within 256B chunk
        const float* base = t3 + (((b * 32 + c) * 192 + y * 8 + rp) * 192)
                               + xbase * 8 + sl * 4;
        float4 m = make_float4(-FLT_MAX, -FLT_MAX, -FLT_MAX, -FLT_MAX);
        #pragma unroll
        for (int i = 0; i < 4; ++i) {             // rows 2i+rp
            float4 v = ldcs4(base + i * 384);
            m.x = fmaxf(m.x, v.x); m.y = fmaxf(m.y, v.y);
            m.z = fmaxf(m.z, v.z); m.w = fmaxf(m.w, v.w);
        }
        float s = hmax4(m);
        s = fmaxf(s, __shfl_xor_sync(FULL, s, 1));  // window = 2 slots (32B)
        s = fmaxf(s, __shfl_xor_sync(FULL, s, 16)); // combine row parities
        if (lane < 16 && (lane & 1) == 0) p3s[c * HX + (sl >> 1)] = s;
    }

    // ---- t2: k=4, 64 ch. Warp handles c = w*8 .. w*8+7. One LDG per c:
    // 4 rows x 128B line-aligned chunks. Lane float4 = one window.
    #pragma unroll
    for (int ci = 0; ci < 8; ++ci) {
        const int c   = w * 8 + ci;
        const int row = lane >> 3;
        const int sl  = lane & 7;                 // window index
        const float* p = t2 + (((b * 64 + c) * 96 + y * 4 + row) * 96)
                            + xbase * 4 + sl * 4;
        float4 v = ldcs4(p);
        float s = hmax4(v);
        s = fmaxf(s, __shfl_xor_sync(FULL, s, 8));  // combine 4 rows
        s = fmaxf(s, __shfl_xor_sync(FULL, s, 16));
        if (lane < 8) p2s[c * HX + lane] = s;
    }

    // ---- t1: k=2, 128 ch. Warp handles 16 ch as 4 LDGs of (4 ch x 2 rows x 64B).
    // Lane float4 = 2 adjacent windows of one row.
    #pragma unroll
    for (int ci = 0; ci < 4; ++ci) {
        const int c   = w * 16 + ci * 4 + (lane >> 3);
        const int row = (lane >> 2) & 1;
        const int sl  = lane & 3;
        const float* p = t1 + (((b * 128 + c) * 48 + y * 2 + row) * 48)
                            + xbase * 2 + sl * 4;
        float4 v = ldcs4(p);
        float o0 = fmaxf(v.x, v.y);
        float o1 = fmaxf(v.z, v.w);
        o0 = fmaxf(o0, __shfl_xor_sync(FULL, o0, 4));   // combine 2 rows
        o1 = fmaxf(o1, __shfl_xor_sync(FULL, o1, 4));
        if (((lane >> 2) & 1) == 0) {
            p1s[c * HX + sl * 2 + 0] = o0;
            p1s[c * HX + sl * 2 + 1] = o1;
        }
    }

    __syncthreads();

    // ---- assemble: 2 float4 items per thread, ff already in registers.
    {
        const int c1 = cA & 127, c2 = cA & 63, c3 = cA & 31, c4 = cA & 15;
        float4 a1 = *reinterpret_cast<const float4*>(&p1s[c1 * HX + xA]);
        float4 a2 = *reinterpret_cast<const float4*>(&p2s[c2 * HX + xA]);
        float4 a3 = *reinterpret_cast<const float4*>(&p3s[c3 * HX + xA]);
        float4 a4 = *reinterpret_cast<const float4*>(&p4s[c4 * HX + xA]);
        float4 r;
        r.x = fmaxf(fA.x + a1.x + a2.x + a3.x + a4.x, 0.f);
        r.y = fmaxf(fA.y + a1.y + a2.y + a3.y + a4.y, 0.f);
        r.z = fmaxf(fA.z + a1.z + a2.z + a3.z + a4.z, 0.f);
        r.w = fmaxf(fA.w + a1.w + a2.w + a3.w + a4.w, 0.f);
        __stcs(reinterpret_cast<float4*>(out + gA), r);
    }
    {
        const int c1 = cB & 127, c2 = cB & 63, c3 = cB & 31, c4 = cB & 15;
        float4 a1 = *reinterpret_cast<const float4*>(&p1s[c1 * HX + xB]);
        float4 a2 = *reinterpret_cast<const float4*>(&p2s[c2 * HX + xB]);
        float4 a3 = *reinterpret_cast<const float4*>(&p3s[c3 * HX + xB]);
        float4 a4 = *reinterpret_cast<const float4*>(&p4s[c4 * HX + xB]);
        float4 r;
        r.x = fmaxf(fB.x + a1.x + a2.x + a3.x + a4.x, 0.f);
        r.y = fmaxf(fB.y + a1.y + a2.y + a3.y + a4.y, 0.f);
        r.z = fmaxf(fB.z + a1.z + a2.z + a3.z + a4.z, 0.f);
        r.w = fmaxf(fB.w + a1.w + a2.w + a3.w + a4.w, 0.f);
        __stcs(reinterpret_cast<float4*>(out + gB), r);
    }
}

extern "C" void kernel_launch(void* const* d_in, const int* in_sizes, int n_in,
                              void* d_out, int out_size) {
    const float* t1 = (const float*)d_in[0];
    const float* t2 = (const float*)d_in[1];
    const float* t3 = (const float*)d_in[2];
    const float* t4 = (const float*)d_in[3];
    const float* ff = (const float*)d_in[4];
    float* out = (float*)d_out;

    dim3 grid(16 * HW * 3);   // 1152 CTAs; occ 4 -> ~1.95 waves
    dim3 block(THREADS);
    fused_ffblock_kernel<<<grid, block>>>(t1, t2, t3, t4, ff, out);
}

// round 10
// speedup vs baseline: 1.0735x; 1.0110x over previous
#include <cuda_runtime.h>
#include <float.h>

// Fused: out[b,c,y,x] = relu( p1[b,c%128,y,x] + p2[b,c%64,y,x]
//                           + p3[b,c%32,y,x] + p4[b,c%16,y,x] + ff[b,c,y,x] )
// pk = non-overlapping max-pool of input_tensor_k.
//
// R7 configuration (best measured: 47.6us kernel, 6.29 TB/s):
//   - one CTA per (b, y, x-third), HX=8; 1152 CTAs x 256 thr, occ 4
//     (~1.95 waves; work-stealing amortizes between-SM completion spread)
//   - warp-coalesced LDG.128s (nL=4 minimum wavefronts) + shfl_xor window
//     reductions (fixes the L1tex wavefront-pump bottleneck)
//   - __ldcs/__stcs streaming hints (data touched exactly once)
// Single change vs R7: t4 inner unroll 4 -> 8 (t4 = 50% of traffic; deeper
// per-warp load batching now that no prefetch registers are held live).

#define HW 24
#define HX 8
#define THREADS 256
#define FULL 0xFFFFFFFFu

__device__ __forceinline__ float hmax4(float4 v) {
    return fmaxf(fmaxf(v.x, v.y), fmaxf(v.z, v.w));
}

__device__ __forceinline__ float4 ldcs4(const float* p) {
    return __ldcs(reinterpret_cast<const float4*>(p));
}

__global__ __launch_bounds__(THREADS, 4)
void fused_ffblock_kernel(const float* __restrict__ t1,   // [16,128,48,48]
                          const float* __restrict__ t2,   // [16, 64,96,96]
                          const float* __restrict__ t3,   // [16, 32,192,192]
                          const float* __restrict__ t4,   // [16, 16,384,384]
                          const float* __restrict__ ff,   // [16,256,24,24]
                          float* __restrict__ out)        // [16,256,24,24]
{
    const int bx   = blockIdx.x;
    const int xh   = bx % 3;
    const int y    = (bx / 3) % HW;
    const int b    = bx / (3 * HW);
    const int tid  = threadIdx.x;
    const int w    = tid >> 5;
    const int lane = tid & 31;
    const int xbase = xh * HX;

    __shared__ __align__(16) float p4s[16 * HX];
    __shared__ __align__(16) float p3s[32 * HX];
    __shared__ __align__(16) float p2s[64 * HX];
    __shared__ __align__(16) float p1s[128 * HX];

    // ---- t4: k=16, 16 ch. Warp handles c = w, w+8. Each LDG: 512B contiguous
    // (one window-row: 8 windows x 16 floats), 16 rows accumulated.
    #pragma unroll
    for (int ci = 0; ci < 2; ++ci) {
        const int c = w + ci * 8;
        const float* base = t4 + (((b * 16 + c) * 384 + y * 16) * 384)
                               + xbase * 16 + lane * 4;
        float4 m = make_float4(-FLT_MAX, -FLT_MAX, -FLT_MAX, -FLT_MAX);
        #pragma unroll 8
        for (int r = 0; r < 16; ++r) {
            float4 v = ldcs4(base + r * 384);
            m.x = fmaxf(m.x, v.x); m.y = fmaxf(m.y, v.y);
            m.z = fmaxf(m.z, v.z); m.w = fmaxf(m.w, v.w);
        }
        float s = hmax4(m);                        // this lane's 16B slot
        s = fmaxf(s, __shfl_xor_sync(FULL, s, 1)); // window = 4 lanes (64B)
        s = fmaxf(s, __shfl_xor_sync(FULL, s, 2));
        if ((lane & 3) == 0) p4s[c * HX + (lane >> 2)] = s;
    }

    // ---- t3: k=8, 32 ch. Warp handles c = w, w+8, w+16, w+24. Each LDG:
    // lanes 0-15 = row 2i (256B), lanes 16-31 = row 2i+1.
    #pragma unroll
    for (int ci = 0; ci < 4; ++ci) {
        const int c  = w + ci * 8;
        const int rp = lane >> 4;                 // row parity
        const int sl = lane & 15;                 // 16B slot within 256B chunk
        const float* base = t3 + (((b * 32 + c) * 192 + y * 8 + rp) * 192)
                               + xbase * 8 + sl * 4;
        float4 m = make_float4(-FLT_MAX, -FLT_MAX, -FLT_MAX, -FLT_MAX);
        #pragma unroll
        for (int i = 0; i < 4; ++i) {             // rows 2i+rp
            float4 v = ldcs4(base + i * 384);
            m.x = fmaxf(m.x, v.x); m.y = fmaxf(m.y, v.y);
            m.z = fmaxf(m.z, v.z); m.w = fmaxf(m.w, v.w);
        }
        float s = hmax4(m);
        s = fmaxf(s, __shfl_xor_sync(FULL, s, 1));  // window = 2 slots (32B)
        s = fmaxf(s, __shfl_xor_sync(FULL, s, 16)); // combine row parities
        if (lane < 16 && (lane & 1) == 0) p3s[c * HX + (sl >> 1)] = s;
    }

    // ---- t2: k=4, 64 ch. Warp handles c = w*8 .. w*8+7. One LDG per c:
    // 4 rows x 128B line-aligned chunks. Lane float4 = one window.
    #pragma unroll
    for (int ci = 0; ci < 8; ++ci) {
        const int c   = w * 8 + ci;
        const int row = lane >> 3;
        const int sl  = lane & 7;                 // window index
        const float* p = t2 + (((b * 64 + c) * 96 + y * 4 + row) * 96)
                            + xbase * 4 + sl * 4;
        float4 v = ldcs4(p);
        float s = hmax4(v);
        s = fmaxf(s, __shfl_xor_sync(FULL, s, 8));  // combine 4 rows
        s = fmaxf(s, __shfl_xor_sync(FULL, s, 16));
        if (lane < 8) p2s[c * HX + lane] = s;
    }

    // ---- t1: k=2, 128 ch. Warp handles 16 ch as 4 LDGs of (4 ch x 2 rows x 64B).
    // Lane float4 = 2 adjacent windows of one row.
    #pragma unroll
    for (int ci = 0; ci < 4; ++ci) {
        const int c   = w * 16 + ci * 4 + (lane >> 3);
        const int row = (lane >> 2) & 1;
        const int sl  = lane & 3;
        const float* p = t1 + (((b * 128 + c) * 48 + y * 2 + row) * 48)
                            + xbase * 2 + sl * 4;
        float4 v = ldcs4(p);
        float o0 = fmaxf(v.x, v.y);
        float o1 = fmaxf(v.z, v.w);
        o0 = fmaxf(o0, __shfl_xor_sync(FULL, o0, 4));   // combine 2 rows
        o1 = fmaxf(o1, __shfl_xor_sync(FULL, o1, 4));
        if (((lane >> 2) & 1) == 0) {
            p1s[c * HX + sl * 2 + 0] = o0;
            p1s[c * HX + sl * 2 + 1] = o1;
        }
    }

    __syncthreads();

    // ---- assemble: 256 ch x 8 x = 512 float4 items (2 per thread).
    const int row_base = ((b * 256) * HW + y) * HW + xbase;
    #pragma unroll
    for (int j = tid; j < 256 * (HX / 4); j += THREADS) {
        const int c  = j >> 1;
        const int x0 = (j & 1) * 4;
        const int c1 = c & 127, c2 = c & 63, c3 = c & 31, c4 = c & 15;
        const int g  = row_base + c * (HW * HW) + x0;

        float4 f  = __ldcs(reinterpret_cast<const float4*>(ff + g));
        float4 a1 = *reinterpret_cast<const float4*>(&p1s[c1 * HX + x0]);
        float4 a2 = *reinterpret_cast<const float4*>(&p2s[c2 * HX + x0]);
        float4 a3 = *reinterpret_cast<const float4*>(&p3s[c3 * HX + x0]);
        float4 a4 = *reinterpret_cast<const float4*>(&p4s[c4 * HX + x0]);

        float4 r;
        r.x = fmaxf(f.x + a1.x + a2.x + a3.x + a4.x, 0.f);
        r.y = fmaxf(f.y + a1.y + a2.y + a3.y + a4.y, 0.f);
        r.z = fmaxf(f.z + a1.z + a2.z + a3.z + a4.z, 0.f);
        r.w = fmaxf(f.w + a1.w + a2.w + a3.w + a4.w, 0.f);

        __stcs(reinterpret_cast<float4*>(out + g), r);
    }
}

extern "C" void kernel_launch(void* const* d_in, const int* in_sizes, int n_in,
                              void* d_out, int out_size) {
    const float* t1 = (const float*)d_in[0];
    const float* t2 = (const float*)d_in[1];
    const float* t3 = (const float*)d_in[2];
    const float* t4 = (const float*)d_in[3];
    const float* ff = (const float*)d_in[4];
    float* out = (float*)d_out;

    dim3 grid(16 * HW * 3);   // 1152 CTAs; occ 4 -> ~1.95 waves
    dim3 block(THREADS);
    fused_ffblock_kernel<<<grid, block>>>(t1, t2, t3, t4, ff, out);
}